// round 3
// baseline (speedup 1.0000x reference)
#include <cuda_runtime.h>
#include <cuda_bf16.h>
#include <mma.h>
#include <cstdint>

using namespace nvcuda;

#define B_  2
#define S_  2048
#define D_  2048
#define H_  16
#define HD_ 128
#define M_  (B_ * S_)      // 4096 token rows

// ---------------- scratch (device globals; no dynamic allocation) ----------------
__device__ float g_h   [(size_t)M_ * D_];        // normalized activations (GEMM A)
__device__ float g_qkv [(size_t)M_ * 3 * D_];    // qkv projections
__device__ float g_attn[(size_t)M_ * D_];        // attention output
__device__ float g_x1  [(size_t)M_ * D_];        // post-residual-1
__device__ float g_ffn [(size_t)M_ * 4 * D_];    // FFN intermediate

// ---------------- cp.async helpers ----------------
__device__ __forceinline__ void cp_async16(void* smem_dst, const void* gmem_src) {
    unsigned int s = (unsigned int)__cvta_generic_to_shared(smem_dst);
    asm volatile("cp.async.cg.shared.global [%0], [%1], 16;\n" :: "r"(s), "l"(gmem_src));
}
__device__ __forceinline__ void cp_commit() {
    asm volatile("cp.async.commit_group;\n");
}
__device__ __forceinline__ void cp_wait0() {
    asm volatile("cp.async.wait_group 0;\n");
}

// ---------------- rmsnorm ----------------
__global__ void rmsnorm_kernel(const float* __restrict__ x, const float* __restrict__ g,
                               float* __restrict__ out) {
    int row = blockIdx.x;
    const float* xr = x + (size_t)row * D_;
    float* orow = out + (size_t)row * D_;
    float ss = 0.f;
    for (int i = threadIdx.x; i < D_; i += 256) { float v = xr[i]; ss += v * v; }
    __shared__ float red[8];
    #pragma unroll
    for (int o = 16; o > 0; o >>= 1) ss += __shfl_xor_sync(0xffffffffu, ss, o);
    if ((threadIdx.x & 31) == 0) red[threadIdx.x >> 5] = ss;
    __syncthreads();
    if (threadIdx.x < 8) {
        float v = red[threadIdx.x];
        #pragma unroll
        for (int o = 4; o > 0; o >>= 1) v += __shfl_xor_sync(0xffu, v, o);
        if (threadIdx.x == 0) red[0] = v;
    }
    __syncthreads();
    float inv = rsqrtf(red[0] / (float)D_ + 1e-6f);
    for (int i = threadIdx.x; i < D_; i += 256) orow[i] = g[i] * xr[i] * inv;
}

// ---------------- tf32 GEMM: C[M,N] = act(A[M,K] @ B[N,K]^T) + res ----------------
// 128x128 block tile, BK=32, 2-stage cp.async pipeline, 8 warps (4x2), warp tile 32x64.
// ACT: 0 = none, 1 = tanh-gelu.  res may be null.
template <int ACT>
__global__ __launch_bounds__(256) void gemm_tf32(const float* __restrict__ A,
                                                 const float* __restrict__ Bm,
                                                 float* __restrict__ C,
                                                 const float* __restrict__ res,
                                                 int M, int N, int K) {
    extern __shared__ float smem[];
    // layout: As[2][128][36], Bs[2][128][36]  (73728 bytes); staging reuses same space
    float (*As)[128][36] = (float (*)[128][36])smem;
    float (*Bs)[128][36] = (float (*)[128][36])(smem + 2 * 128 * 36);

    int bm = blockIdx.y * 128, bn = blockIdx.x * 128;
    int tid = threadIdx.x, warp = tid >> 5;
    int wm = warp >> 1, wn = warp & 1;

    wmma::fragment<wmma::accumulator, 16, 16, 8, float> acc[2][4];
    #pragma unroll
    for (int i = 0; i < 2; i++)
        #pragma unroll
        for (int j = 0; j < 4; j++) wmma::fill_fragment(acc[i][j], 0.f);

    const int NT = K / 32;

    // prologue: tile 0 -> buffer 0
    #pragma unroll
    for (int i = tid; i < 1024; i += 256) {
        int r = i >> 3, c = (i & 7) << 2;
        cp_async16(&As[0][r][c], &A[(size_t)(bm + r) * K + c]);
        cp_async16(&Bs[0][r][c], &Bm[(size_t)(bn + r) * K + c]);
    }
    cp_commit();

    for (int t = 0; t < NT; t++) {
        cp_wait0();
        __syncthreads();                    // tile t resident in buffer t&1
        if (t + 1 < NT) {
            int k0 = (t + 1) * 32, nb = (t + 1) & 1;
            #pragma unroll
            for (int i = tid; i < 1024; i += 256) {
                int r = i >> 3, c = (i & 7) << 2;
                cp_async16(&As[nb][r][c], &A[(size_t)(bm + r) * K + k0 + c]);
                cp_async16(&Bs[nb][r][c], &Bm[(size_t)(bn + r) * K + k0 + c]);
            }
            cp_commit();
        }
        int buf = t & 1;
        #pragma unroll
        for (int kk = 0; kk < 32; kk += 8) {
            wmma::fragment<wmma::matrix_a, 16, 16, 8, wmma::precision::tf32, wmma::row_major> af[2];
            wmma::fragment<wmma::matrix_b, 16, 16, 8, wmma::precision::tf32, wmma::col_major> bf[4];
            #pragma unroll
            for (int i = 0; i < 2; i++) {
                wmma::load_matrix_sync(af[i], &As[buf][wm * 32 + i * 16][kk], 36);
                #pragma unroll
                for (int e = 0; e < af[i].num_elements; e++)
                    af[i].x[e] = wmma::__float_to_tf32(af[i].x[e]);
            }
            #pragma unroll
            for (int j = 0; j < 4; j++) {
                wmma::load_matrix_sync(bf[j], &Bs[buf][wn * 64 + j * 16][kk], 36);
                #pragma unroll
                for (int e = 0; e < bf[j].num_elements; e++)
                    bf[j].x[e] = wmma::__float_to_tf32(bf[j].x[e]);
            }
            #pragma unroll
            for (int i = 0; i < 2; i++)
                #pragma unroll
                for (int j = 0; j < 4; j++)
                    wmma::mma_sync(acc[i][j], af[i], bf[j], acc[i][j]);
        }
        __syncthreads();                    // compute(t) done before overwriting buf at t+1
    }

    // epilogue: stage through smem (reuse pipeline buffers), fuse act/residual
    float* stage = smem;                    // [128][132]
    #pragma unroll
    for (int i = 0; i < 2; i++)
        #pragma unroll
        for (int j = 0; j < 4; j++)
            wmma::store_matrix_sync(&stage[(size_t)(wm * 32 + i * 16) * 132 + wn * 64 + j * 16],
                                    acc[i][j], 132, wmma::mem_row_major);
    __syncthreads();
    for (int i = tid; i < 128 * 32; i += 256) {
        int r = i >> 5, c4 = (i & 31) << 2;
        float4 v = *(float4*)&stage[(size_t)r * 132 + c4];
        if (ACT == 1) {
            float* p = (float*)&v;
            #pragma unroll
            for (int e = 0; e < 4; e++) {
                float xx = p[e];
                float th = tanhf(0.7978845608028654f * (xx + 0.044715f * xx * xx * xx));
                p[e] = 0.5f * xx * (1.f + th);
            }
        }
        if (res) {
            const float4 rv = *(const float4*)&res[(size_t)(bm + r) * N + bn + c4];
            v.x += rv.x; v.y += rv.y; v.z += rv.z; v.w += rv.w;
        }
        *(float4*)&C[(size_t)(bm + r) * N + bn + c4] = v;
    }
}

// ---------------- RoPE (in-place on q,k halves of qkv) ----------------
__global__ void rope_kernel(float* __restrict__ qkv, const float* __restrict__ cs,
                            const float* __restrict__ sn) {
    int idx = blockIdx.x * 256 + threadIdx.x;     // M_*H_*64 threads
    if (idx >= M_ * H_ * 64) return;
    int d = idx & 63;
    int h = (idx >> 6) & 15;
    int row = idx >> 10;
    int s = row & (S_ - 1);
    float c0 = cs[s * HD_ + d],      s0 = sn[s * HD_ + d];
    float c1 = cs[s * HD_ + d + 64], s1 = sn[s * HD_ + d + 64];
    #pragma unroll
    for (int p = 0; p < 2; p++) {                 // p=0: q, p=1: k
        size_t base = (size_t)row * (3 * D_) + (size_t)p * D_ + h * HD_;
        float a = qkv[base + d], b = qkv[base + d + 64];
        qkv[base + d]      = a * c0 - b * s0;
        qkv[base + d + 64] = b * c1 + a * s1;
    }
}

// ---------------- flash attention (causal), tf32 WMMA ----------------
struct FaSmem {
    float Qs[64][132];
    float Ks[64][132];   // also reused as PV scratch
    float Vs[64][132];
    float Ps[64][68];
    float Os[64][128];
    float mrow[64], lrow[64], alpha[64];
};

__global__ __launch_bounds__(256) void flash_kernel(const float* __restrict__ qkv,
                                                    float* __restrict__ attn) {
    extern __shared__ char smem_raw[];
    FaSmem& s = *reinterpret_cast<FaSmem*>(smem_raw);
    int b = blockIdx.z, h = blockIdx.y, q0 = blockIdx.x * 64;
    int tid = threadIdx.x, warp = tid >> 5;
    int wm = warp >> 1, wn = warp & 1;
    const float scale = 0.08838834764831845f;     // 1/sqrt(128)

    size_t qbase = ((size_t)(b * S_ + q0)) * (3 * D_) + h * HD_;
    for (int i = tid; i < 64 * 32; i += 256) {
        int r = i >> 5, c = (i & 31) << 2;
        float4 v = *(const float4*)&qkv[qbase + (size_t)r * (3 * D_) + c];
        v.x *= scale; v.y *= scale; v.z *= scale; v.w *= scale;
        *(float4*)&s.Qs[r][c] = v;
    }
    for (int i = tid; i < 64 * 128; i += 256) ((float*)s.Os)[i] = 0.f;
    if (tid < 64) { s.mrow[tid] = -1e30f; s.lrow[tid] = 0.f; }

    size_t kbase = ((size_t)(b * S_)) * (3 * D_) + D_ + h * HD_;
    size_t vbase = kbase + D_;

    for (int j0 = 0; j0 <= q0; j0 += 64) {
        __syncthreads();   // protects Ks scratch (prev iter) + first-iter init
        for (int i = tid; i < 64 * 32; i += 256) {
            int r = i >> 5, c = (i & 31) << 2;
            *(float4*)&s.Ks[r][c] = *(const float4*)&qkv[kbase + (size_t)(j0 + r) * (3 * D_) + c];
            *(float4*)&s.Vs[r][c] = *(const float4*)&qkv[vbase + (size_t)(j0 + r) * (3 * D_) + c];
        }
        __syncthreads();

        // S = Q K^T  (64x64, K=128); warp tile 16x32
        wmma::fragment<wmma::accumulator, 16, 16, 8, float> accs[2];
        wmma::fill_fragment(accs[0], 0.f);
        wmma::fill_fragment(accs[1], 0.f);
        #pragma unroll
        for (int kk = 0; kk < 128; kk += 8) {
            wmma::fragment<wmma::matrix_a, 16, 16, 8, wmma::precision::tf32, wmma::row_major> af;
            wmma::load_matrix_sync(af, &s.Qs[wm * 16][kk], 132);
            #pragma unroll
            for (int t = 0; t < af.num_elements; t++) af.x[t] = wmma::__float_to_tf32(af.x[t]);
            #pragma unroll
            for (int j = 0; j < 2; j++) {
                wmma::fragment<wmma::matrix_b, 16, 16, 8, wmma::precision::tf32, wmma::col_major> bf;
                wmma::load_matrix_sync(bf, &s.Ks[wn * 32 + j * 16][kk], 132);
                #pragma unroll
                for (int t = 0; t < bf.num_elements; t++) bf.x[t] = wmma::__float_to_tf32(bf.x[t]);
                wmma::mma_sync(accs[j], af, bf, accs[j]);
            }
        }
        wmma::store_matrix_sync(&s.Ps[wm * 16][wn * 32],      accs[0], 68, wmma::mem_row_major);
        wmma::store_matrix_sync(&s.Ps[wm * 16][wn * 32 + 16], accs[1], 68, wmma::mem_row_major);
        __syncthreads();

        // online softmax: 4 threads per row
        {
            int r = tid >> 2, part = tid & 3;
            bool diag = (j0 == q0);
            float vals[16];
            float mx = -1e30f;
            #pragma unroll
            for (int c = 0; c < 16; c++) {
                int cc = part * 16 + c;
                float v = s.Ps[r][cc];
                if (diag && cc > r) v = -1e30f;
                vals[c] = v;
                mx = fmaxf(mx, v);
            }
            mx = fmaxf(mx, __shfl_xor_sync(0xffffffffu, mx, 1));
            mx = fmaxf(mx, __shfl_xor_sync(0xffffffffu, mx, 2));
            float newm = fmaxf(s.mrow[r], mx);
            float sum = 0.f;
            #pragma unroll
            for (int c = 0; c < 16; c++) {
                float p = (vals[c] <= -1e29f) ? 0.f : __expf(vals[c] - newm);
                s.Ps[r][part * 16 + c] = p;
                sum += p;
            }
            sum += __shfl_xor_sync(0xffffffffu, sum, 1);
            sum += __shfl_xor_sync(0xffffffffu, sum, 2);
            if (part == 0) {
                float al = __expf(s.mrow[r] - newm);
                s.alpha[r] = al;
                s.lrow[r] = s.lrow[r] * al + sum;
                s.mrow[r] = newm;
            }
        }
        __syncthreads();

        // PV (64x128, K=64); warp tile 16x64 -> store into Ks scratch
        wmma::fragment<wmma::accumulator, 16, 16, 8, float> acco[4];
        #pragma unroll
        for (int j = 0; j < 4; j++) wmma::fill_fragment(acco[j], 0.f);
        #pragma unroll
        for (int kk = 0; kk < 64; kk += 8) {
            wmma::fragment<wmma::matrix_a, 16, 16, 8, wmma::precision::tf32, wmma::row_major> af;
            wmma::load_matrix_sync(af, &s.Ps[wm * 16][kk], 68);
            #pragma unroll
            for (int t = 0; t < af.num_elements; t++) af.x[t] = wmma::__float_to_tf32(af.x[t]);
            #pragma unroll
            for (int j = 0; j < 4; j++) {
                wmma::fragment<wmma::matrix_b, 16, 16, 8, wmma::precision::tf32, wmma::row_major> bf;
                wmma::load_matrix_sync(bf, &s.Vs[kk][wn * 64 + j * 16], 132);
                #pragma unroll
                for (int t = 0; t < bf.num_elements; t++) bf.x[t] = wmma::__float_to_tf32(bf.x[t]);
                wmma::mma_sync(acco[j], af, bf, acco[j]);
            }
        }
        #pragma unroll
        for (int j = 0; j < 4; j++)
            wmma::store_matrix_sync(&s.Ks[wm * 16][wn * 64 + j * 16], acco[j], 132,
                                    wmma::mem_row_major);
        __syncthreads();

        for (int i = tid; i < 64 * 128; i += 256) {
            int r = i >> 7, c = i & 127;
            s.Os[r][c] = s.Os[r][c] * s.alpha[r] + s.Ks[r][c];
        }
    }
    __syncthreads();

    size_t obase = ((size_t)(b * S_ + q0)) * D_ + h * HD_;
    for (int i = tid; i < 64 * 128; i += 256) {
        int r = i >> 7, c = i & 127;
        attn[obase + (size_t)r * D_ + c] = s.Os[r][c] / s.lrow[r];
    }
}

// ---------------- launch ----------------
extern "C" void kernel_launch(void* const* d_in, const int* in_sizes, int n_in,
                              void* d_out, int out_size) {
    const float* x     = (const float*)d_in[0];
    const float* cs    = (const float*)d_in[1];
    const float* sn    = (const float*)d_in[2];
    const float* g1    = (const float*)d_in[3];
    const float* g2    = (const float*)d_in[4];
    const float* w_qkv = (const float*)d_in[5];
    const float* w_out = (const float*)d_in[6];
    const float* w_fc1 = (const float*)d_in[7];
    const float* w_fc2 = (const float*)d_in[8];
    float* out = (float*)d_out;

    float *h, *qkv, *attn, *x1, *ffn;
    cudaGetSymbolAddress((void**)&h,    g_h);
    cudaGetSymbolAddress((void**)&qkv,  g_qkv);
    cudaGetSymbolAddress((void**)&attn, g_attn);
    cudaGetSymbolAddress((void**)&x1,   g_x1);
    cudaGetSymbolAddress((void**)&ffn,  g_ffn);

    const int gemm_smem = 2 * 128 * 36 * 2 * (int)sizeof(float);   // 73728
    cudaFuncSetAttribute(gemm_tf32<0>, cudaFuncAttributeMaxDynamicSharedMemorySize, gemm_smem);
    cudaFuncSetAttribute(gemm_tf32<1>, cudaFuncAttributeMaxDynamicSharedMemorySize, gemm_smem);
    cudaFuncSetAttribute(flash_kernel, cudaFuncAttributeMaxDynamicSharedMemorySize,
                         (int)sizeof(FaSmem));

    // 1) rmsnorm1
    rmsnorm_kernel<<<M_, 256>>>(x, g1, h);
    // 2) qkv = h @ w_qkv^T   [4096 x 6144], K=2048
    gemm_tf32<0><<<dim3(6144 / 128, M_ / 128), 256, gemm_smem>>>(h, w_qkv, qkv, nullptr,
                                                                 M_, 3 * D_, D_);
    // 3) RoPE on q,k
    rope_kernel<<<(M_ * H_ * 64) / 256, 256>>>(qkv, cs, sn);
    // 4) causal flash attention
    flash_kernel<<<dim3(S_ / 64, H_, B_), 256, sizeof(FaSmem)>>>(qkv, attn);
    // 5) x1 = x + attn @ w_out^T   (fused residual)
    gemm_tf32<0><<<dim3(D_ / 128, M_ / 128), 256, gemm_smem>>>(attn, w_out, x1, x,
                                                               M_, D_, D_);
    // 6) rmsnorm2
    rmsnorm_kernel<<<M_, 256>>>(x1, g2, h);
    // 7) ffn = gelu(h @ w_fc1^T)   [4096 x 8192], K=2048  (fused gelu)
    gemm_tf32<1><<<dim3(4 * D_ / 128, M_ / 128), 256, gemm_smem>>>(h, w_fc1, ffn, nullptr,
                                                                   M_, 4 * D_, D_);
    // 8) out = x1 + ffn @ w_fc2^T   [4096 x 2048], K=8192  (fused residual)
    gemm_tf32<0><<<dim3(D_ / 128, M_ / 128), 256, gemm_smem>>>(ffn, w_fc2, out, x1,
                                                               M_, D_, 4 * D_);
}

// round 5
// speedup vs baseline: 1.1366x; 1.1366x over previous
#include <cuda_runtime.h>
#include <cuda_bf16.h>
#include <mma.h>
#include <cstdint>

using namespace nvcuda;

#define B_  2
#define S_  2048
#define D_  2048
#define H_  16
#define HD_ 128
#define M_  (B_ * S_)      // 4096 token rows

// ---------------- scratch (device globals; no dynamic allocation) ----------------
__device__ float g_h   [(size_t)M_ * D_];
__device__ float g_qkv [(size_t)M_ * 3 * D_];
__device__ float g_attn[(size_t)M_ * D_];
__device__ float g_x1  [(size_t)M_ * D_];
__device__ float g_ffn [(size_t)M_ * 4 * D_];

// ---------------- cp.async helpers ----------------
__device__ __forceinline__ void cp_async16s(unsigned smem_dst, const void* gmem_src) {
    asm volatile("cp.async.cg.shared.global [%0], [%1], 16;\n" :: "r"(smem_dst), "l"(gmem_src));
}
__device__ __forceinline__ void cp_commit() { asm volatile("cp.async.commit_group;\n"); }
__device__ __forceinline__ void cp_wait0()  { asm volatile("cp.async.wait_group 0;\n"); }
__device__ __forceinline__ void cp_wait1()  { asm volatile("cp.async.wait_group 1;\n"); }

// ---------------- rmsnorm ----------------
__global__ void rmsnorm_kernel(const float* __restrict__ x, const float* __restrict__ g,
                               float* __restrict__ out) {
    int row = blockIdx.x;
    const float* xr = x + (size_t)row * D_;
    float* orow = out + (size_t)row * D_;
    float ss = 0.f;
    for (int i = threadIdx.x; i < D_; i += 256) { float v = xr[i]; ss += v * v; }
    __shared__ float red[8];
    #pragma unroll
    for (int o = 16; o > 0; o >>= 1) ss += __shfl_xor_sync(0xffffffffu, ss, o);
    if ((threadIdx.x & 31) == 0) red[threadIdx.x >> 5] = ss;
    __syncthreads();
    if (threadIdx.x < 8) {
        float v = red[threadIdx.x];
        #pragma unroll
        for (int o = 4; o > 0; o >>= 1) v += __shfl_xor_sync(0xffu, v, o);
        if (threadIdx.x == 0) red[0] = v;
    }
    __syncthreads();
    float inv = rsqrtf(red[0] / (float)D_ + 1e-6f);
    for (int i = threadIdx.x; i < D_; i += 256) orow[i] = g[i] * xr[i] * inv;
}

// ---------------- tf32 GEMM v2: C[M,N] = act(A[M,K] @ B[N,K]^T) + res ----------------
// Block tile 128x256, BK=32, 3-stage cp.async pipeline.
// 8 warps in 2(row) x 4(col); warp tile 64x64 -> 16 acc fragments.
#define GBM 128
#define GBN 256
#define GBK 32
#define GLD 36                               // padded row stride (floats)
#define A_STAGE (GBM * GLD)                  // 4608 floats
#define B_STAGE (GBN * GLD)                  // 9216 floats
#define STAGE_F (A_STAGE + B_STAGE)          // 13824 floats
#define GT_SMEM_BYTES (3 * STAGE_F * 4)      // 165888 bytes

template <int ACT>
__global__ __launch_bounds__(256, 1) void gemm_tc(const float* __restrict__ A,
                                                  const float* __restrict__ Bm,
                                                  float* __restrict__ C,
                                                  const float* __restrict__ res,
                                                  int M, int N, int K) {
    extern __shared__ float smem[];
    unsigned sbase = (unsigned)__cvta_generic_to_shared(smem);

    int tid = threadIdx.x, warp = tid >> 5;
    int wm = warp & 1, wn = warp >> 1;           // 2 x 4
    int bm = blockIdx.y * GBM, bn = blockIdx.x * GBN;

    wmma::fragment<wmma::accumulator, 16, 16, 8, float> acc[4][4];
    #pragma unroll
    for (int i = 0; i < 4; i++)
        #pragma unroll
        for (int j = 0; j < 4; j++) wmma::fill_fragment(acc[i][j], 0.f);

    const int NT = K / GBK;

    auto load_tile = [&](int t) {
        int st = t % 3;
        unsigned a_s = sbase + (unsigned)(st * STAGE_F) * 4u;
        unsigned b_s = a_s + A_STAGE * 4u;
        int k0 = t * GBK;
        // A: 128 rows x 8 float4
        #pragma unroll
        for (int i = tid; i < 1024; i += 256) {
            int r = i >> 3, c4 = i & 7;
            cp_async16s(a_s + (unsigned)(r * GLD + c4 * 4) * 4u,
                        &A[(size_t)(bm + r) * K + k0 + c4 * 4]);
        }
        // B: 256 rows x 8 float4
        #pragma unroll
        for (int i = tid; i < 2048; i += 256) {
            int r = i >> 3, c4 = i & 7;
            cp_async16s(b_s + (unsigned)(r * GLD + c4 * 4) * 4u,
                        &Bm[(size_t)(bn + r) * K + k0 + c4 * 4]);
        }
        cp_commit();
    };

    load_tile(0);
    if (NT > 1) load_tile(1);

    for (int t = 0; t < NT; t++) {
        if (t < NT - 1) cp_wait1(); else cp_wait0();   // tile t resident
        __syncthreads();                               // all warps done with stage being reloaded
        if (t + 2 < NT) load_tile(t + 2);

        int st = t % 3;
        float* As = smem + st * STAGE_F;
        float* Bs = As + A_STAGE;

        #pragma unroll
        for (int kk = 0; kk < GBK; kk += 8) {
            wmma::fragment<wmma::matrix_a, 16, 16, 8, wmma::precision::tf32, wmma::row_major> af[4];
            wmma::fragment<wmma::matrix_b, 16, 16, 8, wmma::precision::tf32, wmma::col_major> bf[4];
            #pragma unroll
            for (int i = 0; i < 4; i++) {
                wmma::load_matrix_sync(af[i], &As[(wm * 64 + i * 16) * GLD + kk], GLD);
                #pragma unroll
                for (int e = 0; e < af[i].num_elements; e++)
                    af[i].x[e] = wmma::__float_to_tf32(af[i].x[e]);
            }
            #pragma unroll
            for (int j = 0; j < 4; j++) {
                wmma::load_matrix_sync(bf[j], &Bs[(wn * 64 + j * 16) * GLD + kk], GLD);
                #pragma unroll
                for (int e = 0; e < bf[j].num_elements; e++)
                    bf[j].x[e] = wmma::__float_to_tf32(bf[j].x[e]);
            }
            #pragma unroll
            for (int i = 0; i < 4; i++)
                #pragma unroll
                for (int j = 0; j < 4; j++)
                    wmma::mma_sync(acc[i][j], af[i], bf[j], acc[i][j]);
        }
        __syncthreads();
    }

    // epilogue: stage through smem (reuse pipeline buffers), fuse act/residual
    float* stage = smem;                    // [128][260]
    #pragma unroll
    for (int i = 0; i < 4; i++)
        #pragma unroll
        for (int j = 0; j < 4; j++)
            wmma::store_matrix_sync(&stage[(size_t)(wm * 64 + i * 16) * 260 + wn * 64 + j * 16],
                                    acc[i][j], 260, wmma::mem_row_major);
    __syncthreads();
    for (int i = tid; i < 128 * 64; i += 256) {
        int r = i >> 6, c4 = (i & 63) << 2;
        float4 v = *(float4*)&stage[(size_t)r * 260 + c4];
        if (ACT == 1) {
            float* p = (float*)&v;
            #pragma unroll
            for (int e = 0; e < 4; e++) {
                float xx = p[e];
                float th = tanhf(0.7978845608028654f * (xx + 0.044715f * xx * xx * xx));
                p[e] = 0.5f * xx * (1.f + th);
            }
        }
        if (res) {
            const float4 rv = *(const float4*)&res[(size_t)(bm + r) * N + bn + c4];
            v.x += rv.x; v.y += rv.y; v.z += rv.z; v.w += rv.w;
        }
        *(float4*)&C[(size_t)(bm + r) * N + bn + c4] = v;
    }
}

// ---------------- RoPE (in-place on q,k halves of qkv) ----------------
__global__ void rope_kernel(float* __restrict__ qkv, const float* __restrict__ cs,
                            const float* __restrict__ sn) {
    int idx = blockIdx.x * 256 + threadIdx.x;
    if (idx >= M_ * H_ * 64) return;
    int d = idx & 63;
    int h = (idx >> 6) & 15;
    int row = idx >> 10;
    int s = row & (S_ - 1);
    float c0 = cs[s * HD_ + d],      s0 = sn[s * HD_ + d];
    float c1 = cs[s * HD_ + d + 64], s1 = sn[s * HD_ + d + 64];
    #pragma unroll
    for (int p = 0; p < 2; p++) {
        size_t base = (size_t)row * (3 * D_) + (size_t)p * D_ + h * HD_;
        float a = qkv[base + d], b = qkv[base + d + 64];
        qkv[base + d]      = a * c0 - b * s0;
        qkv[base + d + 64] = b * c1 + a * s1;
    }
}

// ---------------- flash attention (causal), tf32 WMMA (unchanged from R3 pass) ----------------
struct FaSmem {
    float Qs[64][132];
    float Ks[64][132];
    float Vs[64][132];
    float Ps[64][68];
    float Os[64][128];
    float mrow[64], lrow[64], alpha[64];
};

__global__ __launch_bounds__(256) void flash_kernel(const float* __restrict__ qkv,
                                                    float* __restrict__ attn) {
    extern __shared__ char smem_raw[];
    FaSmem& s = *reinterpret_cast<FaSmem*>(smem_raw);
    int b = blockIdx.z, h = blockIdx.y, q0 = blockIdx.x * 64;
    int tid = threadIdx.x, warp = tid >> 5;
    int wm = warp >> 1, wn = warp & 1;
    const float scale = 0.08838834764831845f;

    size_t qbase = ((size_t)(b * S_ + q0)) * (3 * D_) + h * HD_;
    for (int i = tid; i < 64 * 32; i += 256) {
        int r = i >> 5, c = (i & 31) << 2;
        float4 v = *(const float4*)&qkv[qbase + (size_t)r * (3 * D_) + c];
        v.x *= scale; v.y *= scale; v.z *= scale; v.w *= scale;
        *(float4*)&s.Qs[r][c] = v;
    }
    for (int i = tid; i < 64 * 128; i += 256) ((float*)s.Os)[i] = 0.f;
    if (tid < 64) { s.mrow[tid] = -1e30f; s.lrow[tid] = 0.f; }

    size_t kbase = ((size_t)(b * S_)) * (3 * D_) + D_ + h * HD_;
    size_t vbase = kbase + D_;

    for (int j0 = 0; j0 <= q0; j0 += 64) {
        __syncthreads();
        for (int i = tid; i < 64 * 32; i += 256) {
            int r = i >> 5, c = (i & 31) << 2;
            *(float4*)&s.Ks[r][c] = *(const float4*)&qkv[kbase + (size_t)(j0 + r) * (3 * D_) + c];
            *(float4*)&s.Vs[r][c] = *(const float4*)&qkv[vbase + (size_t)(j0 + r) * (3 * D_) + c];
        }
        __syncthreads();

        wmma::fragment<wmma::accumulator, 16, 16, 8, float> accs[2];
        wmma::fill_fragment(accs[0], 0.f);
        wmma::fill_fragment(accs[1], 0.f);
        #pragma unroll
        for (int kk = 0; kk < 128; kk += 8) {
            wmma::fragment<wmma::matrix_a, 16, 16, 8, wmma::precision::tf32, wmma::row_major> af;
            wmma::load_matrix_sync(af, &s.Qs[wm * 16][kk], 132);
            #pragma unroll
            for (int t = 0; t < af.num_elements; t++) af.x[t] = wmma::__float_to_tf32(af.x[t]);
            #pragma unroll
            for (int j = 0; j < 2; j++) {
                wmma::fragment<wmma::matrix_b, 16, 16, 8, wmma::precision::tf32, wmma::col_major> bf;
                wmma::load_matrix_sync(bf, &s.Ks[wn * 32 + j * 16][kk], 132);
                #pragma unroll
                for (int t = 0; t < bf.num_elements; t++) bf.x[t] = wmma::__float_to_tf32(bf.x[t]);
                wmma::mma_sync(accs[j], af, bf, accs[j]);
            }
        }
        wmma::store_matrix_sync(&s.Ps[wm * 16][wn * 32],      accs[0], 68, wmma::mem_row_major);
        wmma::store_matrix_sync(&s.Ps[wm * 16][wn * 32 + 16], accs[1], 68, wmma::mem_row_major);
        __syncthreads();

        {
            int r = tid >> 2, part = tid & 3;
            bool diag = (j0 == q0);
            float vals[16];
            float mx = -1e30f;
            #pragma unroll
            for (int c = 0; c < 16; c++) {
                int cc = part * 16 + c;
                float v = s.Ps[r][cc];
                if (diag && cc > r) v = -1e30f;
                vals[c] = v;
                mx = fmaxf(mx, v);
            }
            mx = fmaxf(mx, __shfl_xor_sync(0xffffffffu, mx, 1));
            mx = fmaxf(mx, __shfl_xor_sync(0xffffffffu, mx, 2));
            float newm = fmaxf(s.mrow[r], mx);
            float sum = 0.f;
            #pragma unroll
            for (int c = 0; c < 16; c++) {
                float p = (vals[c] <= -1e29f) ? 0.f : __expf(vals[c] - newm);
                s.Ps[r][part * 16 + c] = p;
                sum += p;
            }
            sum += __shfl_xor_sync(0xffffffffu, sum, 1);
            sum += __shfl_xor_sync(0xffffffffu, sum, 2);
            if (part == 0) {
                float al = __expf(s.mrow[r] - newm);
                s.alpha[r] = al;
                s.lrow[r] = s.lrow[r] * al + sum;
                s.mrow[r] = newm;
            }
        }
        __syncthreads();

        wmma::fragment<wmma::accumulator, 16, 16, 8, float> acco[4];
        #pragma unroll
        for (int j = 0; j < 4; j++) wmma::fill_fragment(acco[j], 0.f);
        #pragma unroll
        for (int kk = 0; kk < 64; kk += 8) {
            wmma::fragment<wmma::matrix_a, 16, 16, 8, wmma::precision::tf32, wmma::row_major> af;
            wmma::load_matrix_sync(af, &s.Ps[wm * 16][kk], 68);
            #pragma unroll
            for (int t = 0; t < af.num_elements; t++) af.x[t] = wmma::__float_to_tf32(af.x[t]);
            #pragma unroll
            for (int j = 0; j < 4; j++) {
                wmma::fragment<wmma::matrix_b, 16, 16, 8, wmma::precision::tf32, wmma::row_major> bf;
                wmma::load_matrix_sync(bf, &s.Vs[kk][wn * 64 + j * 16], 132);
                #pragma unroll
                for (int t = 0; t < bf.num_elements; t++) bf.x[t] = wmma::__float_to_tf32(bf.x[t]);
                wmma::mma_sync(acco[j], af, bf, acco[j]);
            }
        }
        #pragma unroll
        for (int j = 0; j < 4; j++)
            wmma::store_matrix_sync(&s.Ks[wm * 16][wn * 64 + j * 16], acco[j], 132,
                                    wmma::mem_row_major);
        __syncthreads();

        for (int i = tid; i < 64 * 128; i += 256) {
            int r = i >> 7, c = i & 127;
            s.Os[r][c] = s.Os[r][c] * s.alpha[r] + s.Ks[r][c];
        }
    }
    __syncthreads();

    size_t obase = ((size_t)(b * S_ + q0)) * D_ + h * HD_;
    for (int i = tid; i < 64 * 128; i += 256) {
        int r = i >> 7, c = i & 127;
        attn[obase + (size_t)r * D_ + c] = s.Os[r][c] / s.lrow[r];
    }
}

// ---------------- launch ----------------
extern "C" void kernel_launch(void* const* d_in, const int* in_sizes, int n_in,
                              void* d_out, int out_size) {
    const float* x     = (const float*)d_in[0];
    const float* cs    = (const float*)d_in[1];
    const float* sn    = (const float*)d_in[2];
    const float* g1    = (const float*)d_in[3];
    const float* g2    = (const float*)d_in[4];
    const float* w_qkv = (const float*)d_in[5];
    const float* w_out = (const float*)d_in[6];
    const float* w_fc1 = (const float*)d_in[7];
    const float* w_fc2 = (const float*)d_in[8];
    float* out = (float*)d_out;

    float *h, *qkv, *attn, *x1, *ffn;
    cudaGetSymbolAddress((void**)&h,    g_h);
    cudaGetSymbolAddress((void**)&qkv,  g_qkv);
    cudaGetSymbolAddress((void**)&attn, g_attn);
    cudaGetSymbolAddress((void**)&x1,   g_x1);
    cudaGetSymbolAddress((void**)&ffn,  g_ffn);

    cudaFuncSetAttribute(gemm_tc<0>, cudaFuncAttributeMaxDynamicSharedMemorySize, GT_SMEM_BYTES);
    cudaFuncSetAttribute(gemm_tc<1>, cudaFuncAttributeMaxDynamicSharedMemorySize, GT_SMEM_BYTES);
    cudaFuncSetAttribute(flash_kernel, cudaFuncAttributeMaxDynamicSharedMemorySize,
                         (int)sizeof(FaSmem));

    // 1) rmsnorm1
    rmsnorm_kernel<<<M_, 256>>>(x, g1, h);
    // 2) qkv = h @ w_qkv^T   [4096 x 6144], K=2048
    gemm_tc<0><<<dim3(6144 / GBN, M_ / GBM), 256, GT_SMEM_BYTES>>>(h, w_qkv, qkv, nullptr,
                                                                   M_, 3 * D_, D_);
    // 3) RoPE on q,k
    rope_kernel<<<(M_ * H_ * 64) / 256, 256>>>(qkv, cs, sn);
    // 4) causal flash attention
    flash_kernel<<<dim3(S_ / 64, H_, B_), 256, sizeof(FaSmem)>>>(qkv, attn);
    // 5) x1 = x + attn @ w_out^T   (fused residual)
    gemm_tc<0><<<dim3(D_ / GBN, M_ / GBM), 256, GT_SMEM_BYTES>>>(attn, w_out, x1, x,
                                                                 M_, D_, D_);
    // 6) rmsnorm2
    rmsnorm_kernel<<<M_, 256>>>(x1, g2, h);
    // 7) ffn = gelu(h @ w_fc1^T)   [4096 x 8192], K=2048  (fused gelu)
    gemm_tc<1><<<dim3(4 * D_ / GBN, M_ / GBM), 256, GT_SMEM_BYTES>>>(h, w_fc1, ffn, nullptr,
                                                                     M_, 4 * D_, D_);
    // 8) out = x1 + ffn @ w_fc2^T   [4096 x 2048], K=8192  (fused residual)
    gemm_tc<0><<<dim3(D_ / GBN, M_ / GBM), 256, GT_SMEM_BYTES>>>(ffn, w_fc2, out, x1,
                                                                 M_, D_, 4 * D_);
}

// round 6
// speedup vs baseline: 1.2048x; 1.0600x over previous
#include <cuda_runtime.h>
#include <cuda_bf16.h>
#include <mma.h>
#include <cstdint>

using namespace nvcuda;

#define B_  2
#define S_  2048
#define D_  2048
#define H_  16
#define HD_ 128
#define M_  (B_ * S_)      // 4096 token rows

// ---------------- scratch (device globals; no dynamic allocation) ----------------
__device__ float g_h   [(size_t)M_ * D_];
__device__ float g_qkv [(size_t)M_ * 3 * D_];
__device__ float g_attn[(size_t)M_ * D_];
__device__ float g_x1  [(size_t)M_ * D_];
__device__ float g_ffn [(size_t)M_ * 4 * D_];
// tf32-rounded weight copies
__device__ float g_wqkv[(size_t)3 * D_ * D_];
__device__ float g_wout[(size_t)D_ * D_];
__device__ float g_wfc1[(size_t)4 * D_ * D_];
__device__ float g_wfc2[(size_t)D_ * 4 * D_];

__device__ __forceinline__ float rtf32(float x) { return wmma::__float_to_tf32(x); }

// ---------------- cp.async helpers ----------------
__device__ __forceinline__ void cp_async16s(unsigned smem_dst, const void* gmem_src) {
    asm volatile("cp.async.cg.shared.global [%0], [%1], 16;\n" :: "r"(smem_dst), "l"(gmem_src));
}
__device__ __forceinline__ void cp_commit() { asm volatile("cp.async.commit_group;\n"); }
__device__ __forceinline__ void cp_wait0()  { asm volatile("cp.async.wait_group 0;\n"); }
__device__ __forceinline__ void cp_wait1()  { asm volatile("cp.async.wait_group 1;\n"); }

// ---------------- weight tf32 pre-round ----------------
__global__ void cvt_tf32_kernel(const float* __restrict__ in, float* __restrict__ out, int n4) {
    int i = blockIdx.x * 256 + threadIdx.x;
    if (i >= n4) return;
    float4 v = ((const float4*)in)[i];
    v.x = rtf32(v.x); v.y = rtf32(v.y); v.z = rtf32(v.z); v.w = rtf32(v.w);
    ((float4*)out)[i] = v;
}

// ---------------- rmsnorm (output rounded to tf32: feeds GEMM A-side only) ----------------
__global__ void rmsnorm_kernel(const float* __restrict__ x, const float* __restrict__ g,
                               float* __restrict__ out) {
    int row = blockIdx.x;
    const float* xr = x + (size_t)row * D_;
    float* orow = out + (size_t)row * D_;
    float ss = 0.f;
    for (int i = threadIdx.x; i < D_; i += 256) { float v = xr[i]; ss += v * v; }
    __shared__ float red[8];
    #pragma unroll
    for (int o = 16; o > 0; o >>= 1) ss += __shfl_xor_sync(0xffffffffu, ss, o);
    if ((threadIdx.x & 31) == 0) red[threadIdx.x >> 5] = ss;
    __syncthreads();
    if (threadIdx.x < 8) {
        float v = red[threadIdx.x];
        #pragma unroll
        for (int o = 4; o > 0; o >>= 1) v += __shfl_xor_sync(0xffu, v, o);
        if (threadIdx.x == 0) red[0] = v;
    }
    __syncthreads();
    float inv = rsqrtf(red[0] / (float)D_ + 1e-6f);
    for (int i = threadIdx.x; i < D_; i += 256) orow[i] = rtf32(g[i] * xr[i] * inv);
}

// ---------------- tf32 GEMM v3: operands pre-rounded; no cvt in mainloop ----------------
// Block tile 128x256, BK=32, 3-stage cp.async pipeline, 8 warps (2x4), warp tile 64x64.
#define GBM 128
#define GBN 256
#define GBK 32
#define GLD 36
#define A_STAGE (GBM * GLD)
#define B_STAGE (GBN * GLD)
#define STAGE_F (A_STAGE + B_STAGE)
#define GT_SMEM_BYTES (3 * STAGE_F * 4)      // 165888

// ACT: 0 none; 1 tanh-gelu with tf32-rounded output (feeds next GEMM's A side)
template <int ACT>
__global__ __launch_bounds__(256, 1) void gemm_tc(const float* __restrict__ A,
                                                  const float* __restrict__ Bm,
                                                  float* __restrict__ C,
                                                  const float* __restrict__ res,
                                                  int M, int N, int K) {
    extern __shared__ float smem[];
    unsigned sbase = (unsigned)__cvta_generic_to_shared(smem);

    int tid = threadIdx.x, warp = tid >> 5;
    int wm = warp & 1, wn = warp >> 1;
    int bm = blockIdx.y * GBM, bn = blockIdx.x * GBN;

    wmma::fragment<wmma::accumulator, 16, 16, 8, float> acc[4][4];
    #pragma unroll
    for (int i = 0; i < 4; i++)
        #pragma unroll
        for (int j = 0; j < 4; j++) wmma::fill_fragment(acc[i][j], 0.f);

    const int NT = K / GBK;

    auto load_tile = [&](int t) {
        int st = t % 3;
        unsigned a_s = sbase + (unsigned)(st * STAGE_F) * 4u;
        unsigned b_s = a_s + A_STAGE * 4u;
        int k0 = t * GBK;
        #pragma unroll
        for (int i = tid; i < 1024; i += 256) {
            int r = i >> 3, c4 = i & 7;
            cp_async16s(a_s + (unsigned)(r * GLD + c4 * 4) * 4u,
                        &A[(size_t)(bm + r) * K + k0 + c4 * 4]);
        }
        #pragma unroll
        for (int i = tid; i < 2048; i += 256) {
            int r = i >> 3, c4 = i & 7;
            cp_async16s(b_s + (unsigned)(r * GLD + c4 * 4) * 4u,
                        &Bm[(size_t)(bn + r) * K + k0 + c4 * 4]);
        }
        cp_commit();
    };

    load_tile(0);
    if (NT > 1) load_tile(1);

    for (int t = 0; t < NT; t++) {
        if (t < NT - 1) cp_wait1(); else cp_wait0();
        __syncthreads();
        if (t + 2 < NT) load_tile(t + 2);

        int st = t % 3;
        float* As = smem + st * STAGE_F;
        float* Bs = As + A_STAGE;

        #pragma unroll
        for (int kk = 0; kk < GBK; kk += 8) {
            wmma::fragment<wmma::matrix_a, 16, 16, 8, wmma::precision::tf32, wmma::row_major> af[4];
            wmma::fragment<wmma::matrix_b, 16, 16, 8, wmma::precision::tf32, wmma::col_major> bf[4];
            #pragma unroll
            for (int i = 0; i < 4; i++)
                wmma::load_matrix_sync(af[i], &As[(wm * 64 + i * 16) * GLD + kk], GLD);
            #pragma unroll
            for (int j = 0; j < 4; j++)
                wmma::load_matrix_sync(bf[j], &Bs[(wn * 64 + j * 16) * GLD + kk], GLD);
            #pragma unroll
            for (int i = 0; i < 4; i++)
                #pragma unroll
                for (int j = 0; j < 4; j++)
                    wmma::mma_sync(acc[i][j], af[i], bf[j], acc[i][j]);
        }
        __syncthreads();
    }

    // epilogue via smem staging, fused act/residual
    float* stage = smem;                    // [128][260]
    #pragma unroll
    for (int i = 0; i < 4; i++)
        #pragma unroll
        for (int j = 0; j < 4; j++)
            wmma::store_matrix_sync(&stage[(size_t)(wm * 64 + i * 16) * 260 + wn * 64 + j * 16],
                                    acc[i][j], 260, wmma::mem_row_major);
    __syncthreads();
    for (int i = tid; i < 128 * 64; i += 256) {
        int r = i >> 6, c4 = (i & 63) << 2;
        float4 v = *(float4*)&stage[(size_t)r * 260 + c4];
        if (ACT == 1) {
            float* p = (float*)&v;
            #pragma unroll
            for (int e = 0; e < 4; e++) {
                float xx = p[e];
                float th = tanhf(0.7978845608028654f * (xx + 0.044715f * xx * xx * xx));
                p[e] = rtf32(0.5f * xx * (1.f + th));
            }
        }
        if (res) {
            const float4 rv = *(const float4*)&res[(size_t)(bm + r) * N + bn + c4];
            v.x += rv.x; v.y += rv.y; v.z += rv.z; v.w += rv.w;
        }
        *(float4*)&C[(size_t)(bm + r) * N + bn + c4] = v;
    }
}

// ---------------- RoPE (in-place; q,k rounded to tf32 for flash) ----------------
__global__ void rope_kernel(float* __restrict__ qkv, const float* __restrict__ cs,
                            const float* __restrict__ sn) {
    int idx = blockIdx.x * 256 + threadIdx.x;
    if (idx >= M_ * H_ * 64) return;
    int d = idx & 63;
    int h = (idx >> 6) & 15;
    int row = idx >> 10;
    int s = row & (S_ - 1);
    float c0 = cs[s * HD_ + d],      s0 = sn[s * HD_ + d];
    float c1 = cs[s * HD_ + d + 64], s1 = sn[s * HD_ + d + 64];
    #pragma unroll
    for (int p = 0; p < 2; p++) {
        size_t base = (size_t)row * (3 * D_) + (size_t)p * D_ + h * HD_;
        float a = qkv[base + d], b = qkv[base + d + 64];
        qkv[base + d]      = rtf32(a * c0 - b * s0);
        qkv[base + d + 64] = rtf32(b * c1 + a * s1);
    }
}

// ---------------- flash attention (causal), tf32 WMMA, no mainloop cvts ----------------
struct FaSmem {
    float Qs[64][132];
    float Ks[64][132];
    float Vs[64][132];
    float Ps[64][68];
    float Os[64][128];
    float mrow[64], lrow[64], alpha[64];
};

__global__ __launch_bounds__(256) void flash_kernel(const float* __restrict__ qkv,
                                                    float* __restrict__ attn) {
    extern __shared__ char smem_raw[];
    FaSmem& s = *reinterpret_cast<FaSmem*>(smem_raw);
    int b = blockIdx.z, h = blockIdx.y, q0 = blockIdx.x * 64;
    int tid = threadIdx.x, warp = tid >> 5;
    int wm = warp >> 1, wn = warp & 1;
    const float scale = 0.08838834764831845f;

    size_t qbase = ((size_t)(b * S_ + q0)) * (3 * D_) + h * HD_;
    for (int i = tid; i < 64 * 32; i += 256) {
        int r = i >> 5, c = (i & 31) << 2;
        float4 v = *(const float4*)&qkv[qbase + (size_t)r * (3 * D_) + c];
        v.x = rtf32(v.x * scale); v.y = rtf32(v.y * scale);
        v.z = rtf32(v.z * scale); v.w = rtf32(v.w * scale);
        *(float4*)&s.Qs[r][c] = v;
    }
    for (int i = tid; i < 64 * 128; i += 256) ((float*)s.Os)[i] = 0.f;
    if (tid < 64) { s.mrow[tid] = -1e30f; s.lrow[tid] = 0.f; }

    size_t kbase = ((size_t)(b * S_)) * (3 * D_) + D_ + h * HD_;
    size_t vbase = kbase + D_;

    for (int j0 = 0; j0 <= q0; j0 += 64) {
        __syncthreads();
        for (int i = tid; i < 64 * 32; i += 256) {
            int r = i >> 5, c = (i & 31) << 2;
            *(float4*)&s.Ks[r][c] = *(const float4*)&qkv[kbase + (size_t)(j0 + r) * (3 * D_) + c];
            float4 vv = *(const float4*)&qkv[vbase + (size_t)(j0 + r) * (3 * D_) + c];
            vv.x = rtf32(vv.x); vv.y = rtf32(vv.y); vv.z = rtf32(vv.z); vv.w = rtf32(vv.w);
            *(float4*)&s.Vs[r][c] = vv;
        }
        __syncthreads();

        wmma::fragment<wmma::accumulator, 16, 16, 8, float> accs[2];
        wmma::fill_fragment(accs[0], 0.f);
        wmma::fill_fragment(accs[1], 0.f);
        #pragma unroll
        for (int kk = 0; kk < 128; kk += 8) {
            wmma::fragment<wmma::matrix_a, 16, 16, 8, wmma::precision::tf32, wmma::row_major> af;
            wmma::load_matrix_sync(af, &s.Qs[wm * 16][kk], 132);
            #pragma unroll
            for (int j = 0; j < 2; j++) {
                wmma::fragment<wmma::matrix_b, 16, 16, 8, wmma::precision::tf32, wmma::col_major> bf;
                wmma::load_matrix_sync(bf, &s.Ks[wn * 32 + j * 16][kk], 132);
                wmma::mma_sync(accs[j], af, bf, accs[j]);
            }
        }
        wmma::store_matrix_sync(&s.Ps[wm * 16][wn * 32],      accs[0], 68, wmma::mem_row_major);
        wmma::store_matrix_sync(&s.Ps[wm * 16][wn * 32 + 16], accs[1], 68, wmma::mem_row_major);
        __syncthreads();

        {
            int r = tid >> 2, part = tid & 3;
            bool diag = (j0 == q0);
            float vals[16];
            float mx = -1e30f;
            #pragma unroll
            for (int c = 0; c < 16; c++) {
                int cc = part * 16 + c;
                float v = s.Ps[r][cc];
                if (diag && cc > r) v = -1e30f;
                vals[c] = v;
                mx = fmaxf(mx, v);
            }
            mx = fmaxf(mx, __shfl_xor_sync(0xffffffffu, mx, 1));
            mx = fmaxf(mx, __shfl_xor_sync(0xffffffffu, mx, 2));
            float newm = fmaxf(s.mrow[r], mx);
            float sum = 0.f;
            #pragma unroll
            for (int c = 0; c < 16; c++) {
                float p = (vals[c] <= -1e29f) ? 0.f : __expf(vals[c] - newm);
                s.Ps[r][part * 16 + c] = rtf32(p);
                sum += p;
            }
            sum += __shfl_xor_sync(0xffffffffu, sum, 1);
            sum += __shfl_xor_sync(0xffffffffu, sum, 2);
            if (part == 0) {
                float al = __expf(s.mrow[r] - newm);
                s.alpha[r] = al;
                s.lrow[r] = s.lrow[r] * al + sum;
                s.mrow[r] = newm;
            }
        }
        __syncthreads();

        wmma::fragment<wmma::accumulator, 16, 16, 8, float> acco[4];
        #pragma unroll
        for (int j = 0; j < 4; j++) wmma::fill_fragment(acco[j], 0.f);
        #pragma unroll
        for (int kk = 0; kk < 64; kk += 8) {
            wmma::fragment<wmma::matrix_a, 16, 16, 8, wmma::precision::tf32, wmma::row_major> af;
            wmma::load_matrix_sync(af, &s.Ps[wm * 16][kk], 68);
            #pragma unroll
            for (int j = 0; j < 4; j++) {
                wmma::fragment<wmma::matrix_b, 16, 16, 8, wmma::precision::tf32, wmma::row_major> bf;
                wmma::load_matrix_sync(bf, &s.Vs[kk][wn * 64 + j * 16], 132);
                wmma::mma_sync(acco[j], af, bf, acco[j]);
            }
        }
        #pragma unroll
        for (int j = 0; j < 4; j++)
            wmma::store_matrix_sync(&s.Ks[wm * 16][wn * 64 + j * 16], acco[j], 132,
                                    wmma::mem_row_major);
        __syncthreads();

        for (int i = tid; i < 64 * 128; i += 256) {
            int r = i >> 7, c = i & 127;
            s.Os[r][c] = s.Os[r][c] * s.alpha[r] + s.Ks[r][c];
        }
    }
    __syncthreads();

    // attn feeds the w_out GEMM A-side: round to tf32 here
    size_t obase = ((size_t)(b * S_ + q0)) * D_ + h * HD_;
    for (int i = tid; i < 64 * 128; i += 256) {
        int r = i >> 7, c = i & 127;
        attn[obase + (size_t)r * D_ + c] = rtf32(s.Os[r][c] / s.lrow[r]);
    }
}

// ---------------- launch ----------------
extern "C" void kernel_launch(void* const* d_in, const int* in_sizes, int n_in,
                              void* d_out, int out_size) {
    const float* x     = (const float*)d_in[0];
    const float* cs    = (const float*)d_in[1];
    const float* sn    = (const float*)d_in[2];
    const float* g1    = (const float*)d_in[3];
    const float* g2    = (const float*)d_in[4];
    const float* w_qkv = (const float*)d_in[5];
    const float* w_out = (const float*)d_in[6];
    const float* w_fc1 = (const float*)d_in[7];
    const float* w_fc2 = (const float*)d_in[8];
    float* out = (float*)d_out;

    float *h, *qkv, *attn, *x1, *ffn, *wq, *wo, *w1, *w2;
    cudaGetSymbolAddress((void**)&h,    g_h);
    cudaGetSymbolAddress((void**)&qkv,  g_qkv);
    cudaGetSymbolAddress((void**)&attn, g_attn);
    cudaGetSymbolAddress((void**)&x1,   g_x1);
    cudaGetSymbolAddress((void**)&ffn,  g_ffn);
    cudaGetSymbolAddress((void**)&wq,   g_wqkv);
    cudaGetSymbolAddress((void**)&wo,   g_wout);
    cudaGetSymbolAddress((void**)&w1,   g_wfc1);
    cudaGetSymbolAddress((void**)&w2,   g_wfc2);

    cudaFuncSetAttribute(gemm_tc<0>, cudaFuncAttributeMaxDynamicSharedMemorySize, GT_SMEM_BYTES);
    cudaFuncSetAttribute(gemm_tc<1>, cudaFuncAttributeMaxDynamicSharedMemorySize, GT_SMEM_BYTES);
    cudaFuncSetAttribute(flash_kernel, cudaFuncAttributeMaxDynamicSharedMemorySize,
                         (int)sizeof(FaSmem));

    // 0) weights -> tf32-rounded copies
    cvt_tf32_kernel<<<(3 * D_ * D_ / 4 + 255) / 256, 256>>>(w_qkv, wq, 3 * D_ * D_ / 4);
    cvt_tf32_kernel<<<(D_ * D_ / 4 + 255) / 256, 256>>>(w_out, wo, D_ * D_ / 4);
    cvt_tf32_kernel<<<(4 * D_ * D_ / 4 + 255) / 256, 256>>>(w_fc1, w1, 4 * D_ * D_ / 4);
    cvt_tf32_kernel<<<(4 * D_ * D_ / 4 + 255) / 256, 256>>>(w_fc2, w2, 4 * D_ * D_ / 4);

    // 1) rmsnorm1 (tf32-rounded h)
    rmsnorm_kernel<<<M_, 256>>>(x, g1, h);
    // 2) qkv = h @ wq^T
    gemm_tc<0><<<dim3(6144 / GBN, M_ / GBM), 256, GT_SMEM_BYTES>>>(h, wq, qkv, nullptr,
                                                                   M_, 3 * D_, D_);
    // 3) RoPE (rounds q,k)
    rope_kernel<<<(M_ * H_ * 64) / 256, 256>>>(qkv, cs, sn);
    // 4) causal flash attention (rounds attn)
    flash_kernel<<<dim3(S_ / 64, H_, B_), 256, sizeof(FaSmem)>>>(qkv, attn);
    // 5) x1 = x + attn @ wo^T
    gemm_tc<0><<<dim3(D_ / GBN, M_ / GBM), 256, GT_SMEM_BYTES>>>(attn, wo, x1, x,
                                                                 M_, D_, D_);
    // 6) rmsnorm2 (tf32-rounded h)
    rmsnorm_kernel<<<M_, 256>>>(x1, g2, h);
    // 7) ffn = gelu(h @ w1^T), rounded
    gemm_tc<1><<<dim3(4 * D_ / GBN, M_ / GBM), 256, GT_SMEM_BYTES>>>(h, w1, ffn, nullptr,
                                                                     M_, 4 * D_, D_);
    // 8) out = x1 + ffn @ w2^T
    gemm_tc<0><<<dim3(D_ / GBN, M_ / GBM), 256, GT_SMEM_BYTES>>>(ffn, w2, out, x1,
                                                                 M_, D_, 4 * D_);
}